// round 14
// baseline (speedup 1.0000x reference)
#include <cuda_runtime.h>
#include <cuda_bf16.h>
#include <cuda_fp16.h>
#include <mma.h>
#include <cstdint>

using namespace nvcuda;

#define FDIM 128
#define SNEI 10
#define KCLU 16
#define NMAX 200704
#define BMAX 20480

typedef unsigned long long ull;

// scratch (__device__ globals per allocation rules)
__device__ float  g_pdot[NMAX];
__device__ float  g_c2[16];
__device__ __half g_prod[(size_t)NMAX * FDIM];
__device__ __half g_comb_h[(size_t)BMAX * 256];
__device__ __half g_comb_l[(size_t)BMAX * 256];
__device__ __half g_w_h[128 * 256];

#define FFMA2(d, a, b, c) \
    asm("fma.rn.f32x2 %0, %1, %2, %3;" : "=l"(d) : "l"(a), "l"(b), "l"(c))
#define PACK2(d, lo, hi) \
    asm("mov.b64 %0, {%1, %2};" : "=l"(d) : "f"(lo), "f"(hi))
#define UNPACK2(lo, hi, v) \
    asm("mov.b64 {%0, %1}, %2;" : "=f"(lo), "=f"(hi) : "l"(v))

// ---------------------------------------------------------------------------
// prep: blocks 0..63 convert W to fp16 (512 thr); block 64 computes c2.
// ---------------------------------------------------------------------------
__global__ __launch_bounds__(512)
void prep_kernel(const float* __restrict__ w,
                 __half* __restrict__ wh,
                 const float* __restrict__ center,
                 float* __restrict__ c2)
{
    if (blockIdx.x < 64) {
        int i = blockIdx.x * 512 + threadIdx.x;
        wh[i] = __float2half(w[i]);
    } else {
        int wp = threadIdx.x >> 5, l = threadIdx.x & 31;
        float4 v = ((const float4*)center)[wp * 32 + l];
        float s = v.x * v.x + v.y * v.y + v.z * v.z + v.w * v.w;
#pragma unroll
        for (int o = 16; o; o >>= 1) s += __shfl_xor_sync(0xffffffffu, s, o);
        if (l == 0) c2[wp] = s;
    }
}

// ---------------------------------------------------------------------------
// Precompute per node n (32 nodes / block, 128 threads = 4 warps):
//   phase 2: scalar quarter-row cross/n2/pdot (proven)
//   phase 3: q = 1/(...), split to fp16 hi/lo
//   phase 4: coef[32,128] = q @ mask via wmma (hi/lo, 3 products)
//            4-warp mapping: m0=(w&1)*16, f0=(w>>1)*64, 64-col loop  [FIXED]
//   phase 5: prod = rows * coef -> fp16
// Dynamic smem (~54 KB).
// ---------------------------------------------------------------------------
#define RS4   132   // fp32 rows stride (floats)
#define QHS   24    // q fp16 stride (halves, 48 B rows)
#define MSKS  136   // mask fp16 stride (halves, 272 B rows)
#define CFS   132   // coef fp32 stride (floats, 528 B rows)

#define OFF_ROWS 0                         // 32*132*4  = 16896
#define OFF_CEN  16896                     // 16*128*4  = 8192 (aliased by partials)
#define OFF_ALP  25088                     // 512
#define OFF_C2   25600                     // 64
#define OFF_QH   25664                     // 32*24*2   = 1536
#define OFF_QL   27200                     // 1536
#define OFF_MSKH 28736                     // 16*136*2  = 4352
#define OFF_MSKL 33088                     // 4352
#define OFF_COEF 37440                     // 32*132*4  = 16896
#define PSMB     54336

__global__ __launch_bounds__(128)
void precompute_kernel(const float* __restrict__ neigh_table,
                       const float* __restrict__ center,
                       const float* __restrict__ alpha,
                       const float* __restrict__ cmask,
                       const float* __restrict__ c2g,
                       __half* __restrict__ prod,
                       float* __restrict__ pdot,
                       int N)
{
    extern __shared__ __align__(16) char smp[];
    float*  rows_s = (float*)(smp + OFF_ROWS);
    float*  cen_s  = (float*)(smp + OFF_CEN);
    float*  alp_s  = (float*)(smp + OFF_ALP);
    float*  c2_s   = (float*)(smp + OFF_C2);
    __half* qh_s   = (__half*)(smp + OFF_QH);
    __half* ql_s   = (__half*)(smp + OFF_QL);
    __half* msk_h  = (__half*)(smp + OFF_MSKH);
    __half* msk_l  = (__half*)(smp + OFF_MSKL);
    float*  coef_s = (float*)(smp + OFF_COEF);

    int t = threadIdx.x;
    int w = t >> 5;
    int base = blockIdx.x * 32;
    int n = t & 31, h = t >> 5;

    // ---- phase 1: stage rows(fp32), center(fp32), mask(fp16 hi/lo), alpha, c2
#pragma unroll
    for (int j = 0; j < 8; j++) {
        int i = j * 128 + t;
        int r = i >> 5, c = i & 31;
        float4 v = make_float4(0.f, 0.f, 0.f, 0.f);
        if (base + r < N)
            v = ((const float4*)neigh_table)[(size_t)(base + r) * 32 + c];
        *(float4*)&rows_s[r * RS4 + c * 4] = v;
    }
#pragma unroll
    for (int j = 0; j < 4; j++) {
        int i = j * 128 + t;
        int r = i >> 5, c = i & 31;
        ((float4*)cen_s)[r * 32 + c] = ((const float4*)center)[r * 32 + c];
        float4 mv = ((const float4*)cmask)[r * 32 + c];
        float mf[4] = {mv.x, mv.y, mv.z, mv.w};
        __half mh[4], ml[4];
#pragma unroll
        for (int e = 0; e < 4; e++) {
            mh[e] = __float2half(mf[e]);
            ml[e] = __float2half(mf[e] - __half2float(mh[e]));
        }
        *(__half2*)&msk_h[r * MSKS + c * 4]     = __halves2half2(mh[0], mh[1]);
        *(__half2*)&msk_h[r * MSKS + c * 4 + 2] = __halves2half2(mh[2], mh[3]);
        *(__half2*)&msk_l[r * MSKS + c * 4]     = __halves2half2(ml[0], ml[1]);
        *(__half2*)&msk_l[r * MSKS + c * 4 + 2] = __halves2half2(ml[2], ml[3]);
    }
    if (t < 32) ((float4*)alp_s)[t] = ((const float4*)alpha)[32 + t];
    if (t < 16) c2_s[t] = c2g[t];
    __syncthreads();

    // ---- phase 2: scalar quarter-row reductions (cross x16, n2, pdot)
    ull crp[16], n2p = 0ull, adp = 0ull;
#pragma unroll
    for (int k = 0; k < 16; k++) crp[k] = 0ull;

    {
        const float4* row = (const float4*)&rows_s[n * RS4 + h * 32];
#pragma unroll
        for (int q = 0; q < 8; q++) {
            float4 x = row[q];
            ull xp0, xp1;
            PACK2(xp0, x.x, x.y);
            PACK2(xp1, x.z, x.w);
            ulonglong2 ap = ((const ulonglong2*)(alp_s + h * 32))[q];
            FFMA2(adp, xp0, ap.x, adp);
            FFMA2(adp, xp1, ap.y, adp);
            FFMA2(n2p, xp0, xp0, n2p);
            FFMA2(n2p, xp1, xp1, n2p);
#pragma unroll
            for (int k = 0; k < 16; k++) {
                ulonglong2 cp = ((const ulonglong2*)(cen_s + k * 128 + h * 32))[q];
                FFMA2(crp[k], xp0, cp.x, crp[k]);
                FFMA2(crp[k], xp1, cp.y, crp[k]);
            }
        }
    }

    float cr[16], n2v, adv;
    {
        float lo, hi;
#pragma unroll
        for (int k = 0; k < 16; k++) { UNPACK2(lo, hi, crp[k]); cr[k] = lo + hi; }
        UNPACK2(lo, hi, n2p); n2v = lo + hi;
        UNPACK2(lo, hi, adp); adv = lo + hi;
    }
    __syncthreads();                    // cen_s dead -> partial buffer
    float* part_s = cen_s;              // [3][32][20] floats
    if (h >= 1) {
        float* p = &part_s[(h - 1) * 640 + n * 20];
#pragma unroll
        for (int k = 0; k < 16; k++) p[k] = cr[k];
        p[16] = n2v;
        p[17] = adv;
    }
    __syncthreads();

    // ---- phase 3: q = 1/(n2 - 2 cross + c2 + 1) -> fp16 hi/lo
    if (h == 0) {
        float n2t = n2v, adt = adv;
#pragma unroll
        for (int p = 0; p < 3; p++) {
            n2t += part_s[p * 640 + n * 20 + 16];
            adt += part_s[p * 640 + n * 20 + 17];
        }
        float bse = n2t + 1.0f;
#pragma unroll
        for (int k = 0; k < 16; k++) {
            float crt = cr[k] + part_s[n * 20 + k] + part_s[640 + n * 20 + k]
                      + part_s[1280 + n * 20 + k];
            float den = fmaf(-2.0f, crt, bse + c2_s[k]);
            float qv = 1.0f / den;
            __half qh16 = __float2half(qv);
            qh_s[n * QHS + k] = qh16;
            ql_s[n * QHS + k] = __float2half(qv - __half2float(qh16));
        }
        if (base + n < N) pdot[base + n] = adt;
    }
    __syncthreads();

    // ---- phase 4: coef[32,128] = q @ mask via wmma (3 products)
    // 4-warp mapping: warps cover (m0, f0) in {0,16} x {0,64}; 64-col loop.
    {
        int m0 = (w & 1) * 16;
        int f0 = (w >> 1) * 64;
        wmma::fragment<wmma::matrix_a, 16, 16, 16, __half, wmma::row_major> aqh, aql;
        wmma::load_matrix_sync(aqh, &qh_s[m0 * QHS], QHS);
        wmma::load_matrix_sync(aql, &ql_s[m0 * QHS], QHS);
#pragma unroll
        for (int ff = 0; ff < 64; ff += 16) {
            wmma::fragment<wmma::matrix_b, 16, 16, 16, __half, wmma::row_major> bmh, bml;
            wmma::load_matrix_sync(bmh, &msk_h[f0 + ff], MSKS);
            wmma::load_matrix_sync(bml, &msk_l[f0 + ff], MSKS);
            wmma::fragment<wmma::accumulator, 16, 16, 16, float> acc;
            wmma::fill_fragment(acc, 0.0f);
            wmma::mma_sync(acc, aqh, bmh, acc);
            wmma::mma_sync(acc, aql, bmh, acc);
            wmma::mma_sync(acc, aqh, bml, acc);
            wmma::store_matrix_sync(&coef_s[m0 * CFS + f0 + ff], acc, CFS,
                                    wmma::mem_row_major);
        }
    }
    __syncthreads();

    // ---- phase 5: prod[n,f] = rows[n,f] * coef[n,f] -> fp16 half2 stores
    {
        int tt = t & 63;
        int hh = t >> 6;                 // 0..1
        int fh = tt * 2;
        int nstart = hh * 16;
        int nlim = min(nstart + 16, N - base);
#pragma unroll 4
        for (int nn = nstart; nn < nlim; nn++) {
            float2 x = *(const float2*)&rows_s[nn * RS4 + fh];
            float2 c = *(const float2*)&coef_s[nn * CFS + fh];
            *(__half2*)&prod[(size_t)(base + nn) * FDIM + fh] =
                __floats2half2_rn(x.x * c.x, x.y * c.y);
        }
    }
}

// ---------------------------------------------------------------------------
// Row kernel: warp per row; gathers fp16 prod rows; emits fp16 hi/lo comb.
// (round-12 proven)
// ---------------------------------------------------------------------------
__global__ __launch_bounds__(256)
void row_kernel(const int* __restrict__ nodes,
                const int* __restrict__ neigh_idx,
                const float* __restrict__ self_table,
                const float* __restrict__ alpha,
                const float* __restrict__ pdot,
                const __half* __restrict__ prod,
                __half* __restrict__ comb_hi,
                __half* __restrict__ comb_lo,
                int B)
{
    int wid = threadIdx.x >> 5, lane = threadIdx.x & 31;
    int b = blockIdx.x * 8 + wid;
    if (b >= B) return;

    int node = nodes[b];
    int idx[SNEI];
#pragma unroll
    for (int s = 0; s < SNEI; s++) idx[s] = neigh_idx[b * SNEI + s];

    float4 sf = ((const float4*)self_table)[(size_t)node * 32 + lane];
    uint2 praw[SNEI];
#pragma unroll
    for (int s = 0; s < SNEI; s++)
        praw[s] = ((const uint2*)(prod + (size_t)idx[s] * FDIM))[lane];
    float pd[SNEI];
#pragma unroll
    for (int s = 0; s < SNEI; s++) pd[s] = pdot[idx[s]];

    float4 al = ((const float4*)alpha)[lane];
    float d = sf.x * al.x + sf.y * al.y + sf.z * al.z + sf.w * al.w;
#pragma unroll
    for (int o = 16; o; o >>= 1) d += __shfl_xor_sync(0xffffffffu, d, o);

    float e[SNEI], sum = 0.f;
#pragma unroll
    for (int s = 0; s < SNEI; s++) {
        float l = fmaxf(d + pd[s], 0.f);
        e[s] = __expf(l);
        sum += e[s];
    }
    float inv = 1.0f / sum;

    float4 agg = make_float4(0.f, 0.f, 0.f, 0.f);
#pragma unroll
    for (int s = 0; s < SNEI; s++) {
        float w = e[s] * inv;
        float2 f01 = __half22float2(*(const __half2*)&praw[s].x);
        float2 f23 = __half22float2(*(const __half2*)&praw[s].y);
        agg.x = fmaf(w, f01.x, agg.x);
        agg.y = fmaf(w, f01.y, agg.y);
        agg.z = fmaf(w, f23.x, agg.z);
        agg.w = fmaf(w, f23.y, agg.w);
    }

    float v[8] = {sf.x, sf.y, sf.z, sf.w, agg.x, agg.y, agg.z, agg.w};
    __half hh[8], ll[8];
#pragma unroll
    for (int i = 0; i < 8; i++) {
        hh[i] = __float2half(v[i]);
        ll[i] = __float2half(v[i] - __half2float(hh[i]));
    }
    __half2* ch = (__half2*)(comb_hi + (size_t)b * 256);
    __half2* cl = (__half2*)(comb_lo + (size_t)b * 256);
    ch[lane * 2]          = __halves2half2(hh[0], hh[1]);
    ch[lane * 2 + 1]      = __halves2half2(hh[2], hh[3]);
    ch[64 + lane * 2]     = __halves2half2(hh[4], hh[5]);
    ch[64 + lane * 2 + 1] = __halves2half2(hh[6], hh[7]);
    cl[lane * 2]          = __halves2half2(ll[0], ll[1]);
    cl[lane * 2 + 1]      = __halves2half2(ll[2], ll[3]);
    cl[64 + lane * 2]     = __halves2half2(ll[4], ll[5]);
    cl[64 + lane * 2 + 1] = __halves2half2(ll[6], ll[7]);
}

// ---------------------------------------------------------------------------
// fp16 wmma GEMM, 2 products: out = relu((Ah + Al) @ W16^T)  (round-12 proven)
// ---------------------------------------------------------------------------
#define GBM  64
#define GBK  64
#define AST  72
#define WST  72
#define A_CH (GBM * AST)
#define W_CH (128 * WST)
#define OFF_AH 0
#define OFF_AL (2 * A_CH)
#define OFF_W  (4 * A_CH)
#define GSMH   (OFF_W + 2 * W_CH)

__global__ __launch_bounds__(256, 2)
void gemm_wmma_kernel(const __half* __restrict__ Ah,
                      const __half* __restrict__ Al,
                      const __half* __restrict__ W16,
                      float* __restrict__ out,
                      int Brows)
{
    extern __shared__ __align__(16) __half smg[];
    __half* Ahs = smg + OFF_AH;
    __half* Als = smg + OFF_AL;
    __half* Ws  = smg + OFF_W;

    int tid = threadIdx.x;
    int w = tid >> 5;
    int wm = w & 1, wn = w >> 1;
    int row0 = blockIdx.x * GBM;
    int m0 = wm * 32, n0 = wn * 32;

    wmma::fragment<wmma::accumulator, 16, 16, 16, float> acc[2][2];
#pragma unroll
    for (int i = 0; i < 2; i++)
#pragma unroll
        for (int j = 0; j < 2; j++)
            wmma::fill_fragment(acc[i][j], 0.0f);

    uint4 pah[2], pal[2], pw[4];

#pragma unroll
    for (int j = 0; j < 2; j++) {
        int i = j * 256 + tid;
        int r = i >> 3, c8 = (i & 7) * 8;
        pah[j] = make_uint4(0, 0, 0, 0);
        pal[j] = make_uint4(0, 0, 0, 0);
        if (row0 + r < Brows) {
            pah[j] = *(const uint4*)&Ah[(size_t)(row0 + r) * 256 + c8];
            pal[j] = *(const uint4*)&Al[(size_t)(row0 + r) * 256 + c8];
        }
    }
#pragma unroll
    for (int j = 0; j < 4; j++) {
        int i = j * 256 + tid;
        int r = i >> 3, c8 = (i & 7) * 8;
        pw[j] = *(const uint4*)&W16[(size_t)r * 256 + c8];
    }
#pragma unroll
    for (int j = 0; j < 2; j++) {
        int i = j * 256 + tid;
        int r = i >> 3, c8 = (i & 7) * 8;
        *(uint4*)&Ahs[r * AST + c8] = pah[j];
        *(uint4*)&Als[r * AST + c8] = pal[j];
    }
#pragma unroll
    for (int j = 0; j < 4; j++) {
        int i = j * 256 + tid;
        int r = i >> 3, c8 = (i & 7) * 8;
        *(uint4*)&Ws[r * WST + c8] = pw[j];
    }
    __syncthreads();

    int buf = 0;
#pragma unroll
    for (int chunk = 0; chunk < 4; chunk++) {
        if (chunk < 3) {
            int kc = (chunk + 1) * GBK;
#pragma unroll
            for (int j = 0; j < 2; j++) {
                int i = j * 256 + tid;
                int r = i >> 3, c8 = (i & 7) * 8;
                pah[j] = make_uint4(0, 0, 0, 0);
                pal[j] = make_uint4(0, 0, 0, 0);
                if (row0 + r < Brows) {
                    pah[j] = *(const uint4*)&Ah[(size_t)(row0 + r) * 256 + kc + c8];
                    pal[j] = *(const uint4*)&Al[(size_t)(row0 + r) * 256 + kc + c8];
                }
            }
#pragma unroll
            for (int j = 0; j < 4; j++) {
                int i = j * 256 + tid;
                int r = i >> 3, c8 = (i & 7) * 8;
                pw[j] = *(const uint4*)&W16[(size_t)r * 256 + kc + c8];
            }
        }

        const __half* Ab_h = Ahs + buf * A_CH;
        const __half* Ab_l = Als + buf * A_CH;
        const __half* Wb   = Ws  + buf * W_CH;
#pragma unroll
        for (int kk = 0; kk < GBK; kk += 16) {
            wmma::fragment<wmma::matrix_a, 16, 16, 16, __half, wmma::row_major> fah[2], fal[2];
            wmma::fragment<wmma::matrix_b, 16, 16, 16, __half, wmma::col_major> fb[2];
#pragma unroll
            for (int i = 0; i < 2; i++) {
                wmma::load_matrix_sync(fah[i], &Ab_h[(m0 + i * 16) * AST + kk], AST);
                wmma::load_matrix_sync(fal[i], &Ab_l[(m0 + i * 16) * AST + kk], AST);
            }
#pragma unroll
            for (int j = 0; j < 2; j++)
                wmma::load_matrix_sync(fb[j], &Wb[(n0 + j * 16) * WST + kk], WST);
#pragma unroll
            for (int i = 0; i < 2; i++)
#pragma unroll
                for (int j = 0; j < 2; j++) {
                    wmma::mma_sync(acc[i][j], fah[i], fb[j], acc[i][j]);
                    wmma::mma_sync(acc[i][j], fal[i], fb[j], acc[i][j]);
                }
        }

        if (chunk < 3) {
            int nb = buf ^ 1;
            __syncthreads();
#pragma unroll
            for (int j = 0; j < 2; j++) {
                int i = j * 256 + tid;
                int r = i >> 3, c8 = (i & 7) * 8;
                *(uint4*)&Ahs[nb * A_CH + r * AST + c8] = pah[j];
                *(uint4*)&Als[nb * A_CH + r * AST + c8] = pal[j];
            }
#pragma unroll
            for (int j = 0; j < 4; j++) {
                int i = j * 256 + tid;
                int r = i >> 3, c8 = (i & 7) * 8;
                *(uint4*)&Ws[nb * W_CH + r * WST + c8] = pw[j];
            }
            __syncthreads();
            buf = nb;
        }
    }

#pragma unroll
    for (int i = 0; i < 2; i++) {
        int gr = row0 + m0 + i * 16;
        if (gr < Brows) {
#pragma unroll
            for (int j = 0; j < 2; j++) {
#pragma unroll
                for (int e = 0; e < acc[i][j].num_elements; e++)
                    acc[i][j].x[e] = fmaxf(acc[i][j].x[e], 0.0f);
                wmma::store_matrix_sync(&out[(size_t)gr * FDIM + n0 + j * 16],
                                        acc[i][j], FDIM, wmma::mem_row_major);
            }
        }
    }
}

// ---------------------------------------------------------------------------
extern "C" void kernel_launch(void* const* d_in, const int* in_sizes, int n_in,
                              void* d_out, int out_size)
{
    const int*   nodes      = (const int*)d_in[0];
    const int*   neigh_idx  = (const int*)d_in[1];
    const float* self_table = (const float*)d_in[2];
    const float* neigh_tab  = (const float*)d_in[3];
    const float* center     = (const float*)d_in[4];
    const float* cmask      = (const float*)d_in[5];
    const float* weight     = (const float*)d_in[6];
    const float* alpha      = (const float*)d_in[7];
    float*       out        = (float*)d_out;

    int B = in_sizes[0];
    int N = in_sizes[3] / FDIM;

    float *pd, *c2;
    __half *prod, *ch, *cl, *wh;
    cudaGetSymbolAddress((void**)&prod, g_prod);
    cudaGetSymbolAddress((void**)&pd,   g_pdot);
    cudaGetSymbolAddress((void**)&c2,   g_c2);
    cudaGetSymbolAddress((void**)&ch,   g_comb_h);
    cudaGetSymbolAddress((void**)&cl,   g_comb_l);
    cudaGetSymbolAddress((void**)&wh,   g_w_h);

    cudaFuncSetAttribute(precompute_kernel,
                         cudaFuncAttributeMaxDynamicSharedMemorySize, PSMB);
    cudaFuncSetAttribute(gemm_wmma_kernel,
                         cudaFuncAttributeMaxDynamicSharedMemorySize,
                         GSMH * (int)sizeof(__half));

    prep_kernel<<<65, 512>>>(weight, wh, center, c2);
    precompute_kernel<<<(N + 31) / 32, 128, PSMB>>>(neigh_tab, center, alpha,
                                                    cmask, c2, prod, pd, N);
    row_kernel<<<(B + 7) / 8, 256>>>(nodes, neigh_idx, self_table, alpha,
                                     pd, prod, ch, cl, B);
    gemm_wmma_kernel<<<(B + GBM - 1) / GBM, 256,
                      GSMH * (int)sizeof(__half)>>>(ch, cl, wh, out, B);
}

// round 15
// speedup vs baseline: 1.0875x; 1.0875x over previous
#include <cuda_runtime.h>
#include <cuda_bf16.h>
#include <cuda_fp16.h>
#include <mma.h>
#include <cstdint>

using namespace nvcuda;

#define FDIM 128
#define SNEI 10
#define KCLU 16
#define NMAX 200704
#define BMAX 20480

typedef unsigned long long ull;

// scratch (__device__ globals per allocation rules)
__device__ float  g_pdot[NMAX];
__device__ float  g_c2[16];
__device__ __half g_prod[(size_t)NMAX * FDIM];
__device__ __half g_comb_h[(size_t)BMAX * 256];
__device__ __half g_comb_l[(size_t)BMAX * 256];
__device__ __half g_w_h[128 * 256];
__device__ unsigned char g_flag[NMAX];
__device__ int    g_list[NMAX];
__device__ int    g_count;

#define FFMA2(d, a, b, c) \
    asm("fma.rn.f32x2 %0, %1, %2, %3;" : "=l"(d) : "l"(a), "l"(b), "l"(c))
#define PACK2(d, lo, hi) \
    asm("mov.b64 %0, {%1, %2};" : "=l"(d) : "f"(lo), "f"(hi))
#define UNPACK2(lo, hi, v) \
    asm("mov.b64 {%0, %1}, %2;" : "=f"(lo), "=f"(hi) : "l"(v))

// ---------------------------------------------------------------------------
// prep: blocks 0..63 convert W to fp16 (512 thr); block 64 computes c2;
// blocks 65.. zero the flag array + counter.
// ---------------------------------------------------------------------------
#define ZBLK 98   // blocks 65..162 zero 200704 bytes as int4 (512 thr * 16 B * 25 iters? no: computed below)

__global__ __launch_bounds__(512)
void prep_kernel(const float* __restrict__ w,
                 __half* __restrict__ wh,
                 const float* __restrict__ center,
                 float* __restrict__ c2,
                 unsigned char* __restrict__ flag,
                 int* __restrict__ count)
{
    if (blockIdx.x < 64) {
        int i = blockIdx.x * 512 + threadIdx.x;
        wh[i] = __float2half(w[i]);
    } else if (blockIdx.x == 64) {
        int wp = threadIdx.x >> 5, l = threadIdx.x & 31;
        float4 v = ((const float4*)center)[wp * 32 + l];
        float s = v.x * v.x + v.y * v.y + v.z * v.z + v.w * v.w;
#pragma unroll
        for (int o = 16; o; o >>= 1) s += __shfl_xor_sync(0xffffffffu, s, o);
        if (l == 0) c2[wp] = s;
        if (threadIdx.x == 0) *count = 0;
    } else {
        // zero flags: NMAX/16 = 12544 int4; blocks 65..89 (25 blocks x 512)
        int i = (blockIdx.x - 65) * 512 + threadIdx.x;
        if (i < NMAX / 16)
            ((int4*)flag)[i] = make_int4(0, 0, 0, 0);
    }
}

// ---------------------------------------------------------------------------
// mark used nodes (plain byte stores; write-write races benign)
// ---------------------------------------------------------------------------
__global__ __launch_bounds__(256)
void flag_kernel(const int* __restrict__ neigh_idx,
                 unsigned char* __restrict__ flag, int total)
{
    int i = blockIdx.x * 256 + threadIdx.x;
    if (i < total) flag[neigh_idx[i]] = 1;
}

// ---------------------------------------------------------------------------
// compact used node ids into g_list (warp-aggregated atomics)
// ---------------------------------------------------------------------------
__global__ __launch_bounds__(256)
void compact_kernel(const unsigned char* __restrict__ flag,
                    int* __restrict__ list, int* __restrict__ count, int N)
{
    int i = blockIdx.x * 256 + threadIdx.x;
    bool used = (i < N) && flag[i];
    unsigned mask = __ballot_sync(0xffffffffu, used);
    int lane = threadIdx.x & 31;
    int cnt = __popc(mask);
    int pos = 0;
    if (lane == 0 && cnt) pos = atomicAdd(count, cnt);
    pos = __shfl_sync(0xffffffffu, pos, 0);
    if (used) list[pos + __popc(mask & ((1u << lane) - 1))] = i;
}

// ---------------------------------------------------------------------------
// Precompute per USED node (32 list entries / block, 128 threads,
// quarter-row split). Round-12 proven math, node-id indirection added.
// ---------------------------------------------------------------------------
#define RS4  132
#define QST  20

__global__ __launch_bounds__(128)
void precompute_kernel(const float* __restrict__ neigh_table,
                       const float* __restrict__ center,
                       const float* __restrict__ alpha,
                       const float* __restrict__ cmask,
                       const float* __restrict__ c2g,
                       const int* __restrict__ list,
                       const int* __restrict__ countp,
                       __half* __restrict__ prod,
                       float* __restrict__ pdot)
{
    __shared__ __align__(16) float rows_s[32 * RS4];
    __shared__ __align__(16) float cen_s[16 * 128];
    __shared__ __align__(16) float alp_s[128];
    __shared__ __align__(16) float q_s[32 * QST];
    __shared__ float c2_s[16];
    __shared__ int nid_s[32];

    int count = *countp;
    int base = blockIdx.x * 32;
    if (base >= count) return;

    int t = threadIdx.x;
    int n = t & 31, h = t >> 5;

    if (t < 32) nid_s[t] = (base + t < count) ? list[base + t] : 0;
    __syncthreads();

    ull mp[8];
#pragma unroll
    for (int kp = 0; kp < 8; kp++) {
        float m0 = cmask[(2 * kp) * FDIM + t];
        float m1 = cmask[(2 * kp + 1) * FDIM + t];
        PACK2(mp[kp], m0, m1);
    }

    // ---- stage 32 rows (via id table) + center + alpha + c2 ----
#pragma unroll
    for (int j = 0; j < 8; j++) {
        int i = j * 128 + t;
        int r = i >> 5, c = i & 31;
        float4 v = make_float4(0.f, 0.f, 0.f, 0.f);
        if (base + r < count)
            v = ((const float4*)neigh_table)[(size_t)nid_s[r] * 32 + c];
        *(float4*)&rows_s[r * RS4 + c * 4] = v;
    }
#pragma unroll
    for (int j = 0; j < 4; j++)
        ((float4*)cen_s)[j * 128 + t] = ((const float4*)center)[j * 128 + t];
    if (t < 32) ((float4*)alp_s)[t] = ((const float4*)alpha)[32 + t];
    if (t < 16) c2_s[t] = c2g[t];
    __syncthreads();

    // ---- phase 2: quarter-row reductions (cross x16, n2, pdot) ----
    ull crp[16], n2p = 0ull, adp = 0ull;
#pragma unroll
    for (int k = 0; k < 16; k++) crp[k] = 0ull;

    {
        const float4* row = (const float4*)&rows_s[n * RS4 + h * 32];
#pragma unroll
        for (int q = 0; q < 8; q++) {
            float4 x = row[q];
            ull xp0, xp1;
            PACK2(xp0, x.x, x.y);
            PACK2(xp1, x.z, x.w);
            ulonglong2 ap = ((const ulonglong2*)(alp_s + h * 32))[q];
            FFMA2(adp, xp0, ap.x, adp);
            FFMA2(adp, xp1, ap.y, adp);
            FFMA2(n2p, xp0, xp0, n2p);
            FFMA2(n2p, xp1, xp1, n2p);
#pragma unroll
            for (int k = 0; k < 16; k++) {
                ulonglong2 cp = ((const ulonglong2*)(cen_s + k * 128 + h * 32))[q];
                FFMA2(crp[k], xp0, cp.x, crp[k]);
                FFMA2(crp[k], xp1, cp.y, crp[k]);
            }
        }
    }

    float cr[16], n2v, adv;
    {
        float lo, hi;
#pragma unroll
        for (int k = 0; k < 16; k++) { UNPACK2(lo, hi, crp[k]); cr[k] = lo + hi; }
        UNPACK2(lo, hi, n2p); n2v = lo + hi;
        UNPACK2(lo, hi, adp); adv = lo + hi;
    }
    __syncthreads();                 // cen_s dead -> partial buffer
    float* part_s = cen_s;           // [3][32][20] floats
    if (h >= 1) {
        float* p = &part_s[(h - 1) * 640 + n * 20];
#pragma unroll
        for (int k = 0; k < 16; k++) p[k] = cr[k];
        p[16] = n2v;
        p[17] = adv;
    }
    __syncthreads();
    if (h == 0) {
        float n2t = n2v, adt = adv;
#pragma unroll
        for (int p = 0; p < 3; p++) {
            n2t += part_s[p * 640 + n * 20 + 16];
            adt += part_s[p * 640 + n * 20 + 17];
        }
        float bse = n2t + 1.0f;
#pragma unroll
        for (int k = 0; k < 16; k++) {
            float crt = cr[k] + part_s[n * 20 + k] + part_s[640 + n * 20 + k]
                      + part_s[1280 + n * 20 + k];
            float den = fmaf(-2.0f, crt, bse + c2_s[k]);
            q_s[n * QST + k] = 1.0f / den;
        }
        if (base + n < count) pdot[nid_s[n]] = adt;
    }
    __syncthreads();

    // ---- phase 3: thread = feature t; loop listed nodes; LDS.128 q loads ----
    int nlim = min(32, count - base);
    for (int nn = 0; nn < nlim; nn++) {
        const ulonglong2* qp2 = (const ulonglong2*)&q_s[nn * QST];
        ull acc = 0ull;
#pragma unroll
        for (int kp = 0; kp < 4; kp++) {
            ulonglong2 qq = qp2[kp];
            FFMA2(acc, qq.x, mp[2 * kp],     acc);
            FFMA2(acc, qq.y, mp[2 * kp + 1], acc);
        }
        float lo, hi; UNPACK2(lo, hi, acc);
        float x = rows_s[nn * RS4 + t];
        prod[(size_t)nid_s[nn] * FDIM + t] = __float2half(x * (lo + hi));
    }
}

// ---------------------------------------------------------------------------
// Row kernel: warp per row; gathers fp16 prod rows; emits fp16 hi/lo comb.
// (round-12 proven)
// ---------------------------------------------------------------------------
__global__ __launch_bounds__(256)
void row_kernel(const int* __restrict__ nodes,
                const int* __restrict__ neigh_idx,
                const float* __restrict__ self_table,
                const float* __restrict__ alpha,
                const float* __restrict__ pdot,
                const __half* __restrict__ prod,
                __half* __restrict__ comb_hi,
                __half* __restrict__ comb_lo,
                int B)
{
    int wid = threadIdx.x >> 5, lane = threadIdx.x & 31;
    int b = blockIdx.x * 8 + wid;
    if (b >= B) return;

    int node = nodes[b];
    int idx[SNEI];
#pragma unroll
    for (int s = 0; s < SNEI; s++) idx[s] = neigh_idx[b * SNEI + s];

    float4 sf = ((const float4*)self_table)[(size_t)node * 32 + lane];
    uint2 praw[SNEI];
#pragma unroll
    for (int s = 0; s < SNEI; s++)
        praw[s] = ((const uint2*)(prod + (size_t)idx[s] * FDIM))[lane];
    float pd[SNEI];
#pragma unroll
    for (int s = 0; s < SNEI; s++) pd[s] = pdot[idx[s]];

    float4 al = ((const float4*)alpha)[lane];
    float d = sf.x * al.x + sf.y * al.y + sf.z * al.z + sf.w * al.w;
#pragma unroll
    for (int o = 16; o; o >>= 1) d += __shfl_xor_sync(0xffffffffu, d, o);

    float e[SNEI], sum = 0.f;
#pragma unroll
    for (int s = 0; s < SNEI; s++) {
        float l = fmaxf(d + pd[s], 0.f);
        e[s] = __expf(l);
        sum += e[s];
    }
    float inv = 1.0f / sum;

    float4 agg = make_float4(0.f, 0.f, 0.f, 0.f);
#pragma unroll
    for (int s = 0; s < SNEI; s++) {
        float w = e[s] * inv;
        float2 f01 = __half22float2(*(const __half2*)&praw[s].x);
        float2 f23 = __half22float2(*(const __half2*)&praw[s].y);
        agg.x = fmaf(w, f01.x, agg.x);
        agg.y = fmaf(w, f01.y, agg.y);
        agg.z = fmaf(w, f23.x, agg.z);
        agg.w = fmaf(w, f23.y, agg.w);
    }

    float v[8] = {sf.x, sf.y, sf.z, sf.w, agg.x, agg.y, agg.z, agg.w};
    __half hh[8], ll[8];
#pragma unroll
    for (int i = 0; i < 8; i++) {
        hh[i] = __float2half(v[i]);
        ll[i] = __float2half(v[i] - __half2float(hh[i]));
    }
    __half2* ch = (__half2*)(comb_hi + (size_t)b * 256);
    __half2* cl = (__half2*)(comb_lo + (size_t)b * 256);
    ch[lane * 2]          = __halves2half2(hh[0], hh[1]);
    ch[lane * 2 + 1]      = __halves2half2(hh[2], hh[3]);
    ch[64 + lane * 2]     = __halves2half2(hh[4], hh[5]);
    ch[64 + lane * 2 + 1] = __halves2half2(hh[6], hh[7]);
    cl[lane * 2]          = __halves2half2(ll[0], ll[1]);
    cl[lane * 2 + 1]      = __halves2half2(ll[2], ll[3]);
    cl[64 + lane * 2]     = __halves2half2(ll[4], ll[5]);
    cl[64 + lane * 2 + 1] = __halves2half2(ll[6], ll[7]);
}

// ---------------------------------------------------------------------------
// fp16 wmma GEMM, 2 products: out = relu((Ah + Al) @ W16^T)  (round-12 proven)
// ---------------------------------------------------------------------------
#define GBM  64
#define GBK  64
#define AST  72
#define WST  72
#define A_CH (GBM * AST)
#define W_CH (128 * WST)
#define OFF_AH 0
#define OFF_AL (2 * A_CH)
#define OFF_W  (4 * A_CH)
#define GSMH   (OFF_W + 2 * W_CH)

__global__ __launch_bounds__(256, 2)
void gemm_wmma_kernel(const __half* __restrict__ Ah,
                      const __half* __restrict__ Al,
                      const __half* __restrict__ W16,
                      float* __restrict__ out,
                      int Brows)
{
    extern __shared__ __align__(16) __half smg[];
    __half* Ahs = smg + OFF_AH;
    __half* Als = smg + OFF_AL;
    __half* Ws  = smg + OFF_W;

    int tid = threadIdx.x;
    int w = tid >> 5;
    int wm = w & 1, wn = w >> 1;
    int row0 = blockIdx.x * GBM;
    int m0 = wm * 32, n0 = wn * 32;

    wmma::fragment<wmma::accumulator, 16, 16, 16, float> acc[2][2];
#pragma unroll
    for (int i = 0; i < 2; i++)
#pragma unroll
        for (int j = 0; j < 2; j++)
            wmma::fill_fragment(acc[i][j], 0.0f);

    uint4 pah[2], pal[2], pw[4];

#pragma unroll
    for (int j = 0; j < 2; j++) {
        int i = j * 256 + tid;
        int r = i >> 3, c8 = (i & 7) * 8;
        pah[j] = make_uint4(0, 0, 0, 0);
        pal[j] = make_uint4(0, 0, 0, 0);
        if (row0 + r < Brows) {
            pah[j] = *(const uint4*)&Ah[(size_t)(row0 + r) * 256 + c8];
            pal[j] = *(const uint4*)&Al[(size_t)(row0 + r) * 256 + c8];
        }
    }
#pragma unroll
    for (int j = 0; j < 4; j++) {
        int i = j * 256 + tid;
        int r = i >> 3, c8 = (i & 7) * 8;
        pw[j] = *(const uint4*)&W16[(size_t)r * 256 + c8];
    }
#pragma unroll
    for (int j = 0; j < 2; j++) {
        int i = j * 256 + tid;
        int r = i >> 3, c8 = (i & 7) * 8;
        *(uint4*)&Ahs[r * AST + c8] = pah[j];
        *(uint4*)&Als[r * AST + c8] = pal[j];
    }
#pragma unroll
    for (int j = 0; j < 4; j++) {
        int i = j * 256 + tid;
        int r = i >> 3, c8 = (i & 7) * 8;
        *(uint4*)&Ws[r * WST + c8] = pw[j];
    }
    __syncthreads();

    int buf = 0;
#pragma unroll
    for (int chunk = 0; chunk < 4; chunk++) {
        if (chunk < 3) {
            int kc = (chunk + 1) * GBK;
#pragma unroll
            for (int j = 0; j < 2; j++) {
                int i = j * 256 + tid;
                int r = i >> 3, c8 = (i & 7) * 8;
                pah[j] = make_uint4(0, 0, 0, 0);
                pal[j] = make_uint4(0, 0, 0, 0);
                if (row0 + r < Brows) {
                    pah[j] = *(const uint4*)&Ah[(size_t)(row0 + r) * 256 + kc + c8];
                    pal[j] = *(const uint4*)&Al[(size_t)(row0 + r) * 256 + kc + c8];
                }
            }
#pragma unroll
            for (int j = 0; j < 4; j++) {
                int i = j * 256 + tid;
                int r = i >> 3, c8 = (i & 7) * 8;
                pw[j] = *(const uint4*)&W16[(size_t)r * 256 + kc + c8];
            }
        }

        const __half* Ab_h = Ahs + buf * A_CH;
        const __half* Ab_l = Als + buf * A_CH;
        const __half* Wb   = Ws  + buf * W_CH;
#pragma unroll
        for (int kk = 0; kk < GBK; kk += 16) {
            wmma::fragment<wmma::matrix_a, 16, 16, 16, __half, wmma::row_major> fah[2], fal[2];
            wmma::fragment<wmma::matrix_b, 16, 16, 16, __half, wmma::col_major> fb[2];
#pragma unroll
            for (int i = 0; i < 2; i++) {
                wmma::load_matrix_sync(fah[i], &Ab_h[(m0 + i * 16) * AST + kk], AST);
                wmma::load_matrix_sync(fal[i], &Ab_l[(m0 + i * 16) * AST + kk], AST);
            }
#pragma unroll
            for (int j = 0; j < 2; j++)
                wmma::load_matrix_sync(fb[j], &Wb[(n0 + j * 16) * WST + kk], WST);
#pragma unroll
            for (int i = 0; i < 2; i++)
#pragma unroll
                for (int j = 0; j < 2; j++) {
                    wmma::mma_sync(acc[i][j], fah[i], fb[j], acc[i][j]);
                    wmma::mma_sync(acc[i][j], fal[i], fb[j], acc[i][j]);
                }
        }

        if (chunk < 3) {
            int nb = buf ^ 1;
            __syncthreads();
#pragma unroll
            for (int j = 0; j < 2; j++) {
                int i = j * 256 + tid;
                int r = i >> 3, c8 = (i & 7) * 8;
                *(uint4*)&Ahs[nb * A_CH + r * AST + c8] = pah[j];
                *(uint4*)&Als[nb * A_CH + r * AST + c8] = pal[j];
            }
#pragma unroll
            for (int j = 0; j < 4; j++) {
                int i = j * 256 + tid;
                int r = i >> 3, c8 = (i & 7) * 8;
                *(uint4*)&Ws[nb * W_CH + r * WST + c8] = pw[j];
            }
            __syncthreads();
            buf = nb;
        }
    }

#pragma unroll
    for (int i = 0; i < 2; i++) {
        int gr = row0 + m0 + i * 16;
        if (gr < Brows) {
#pragma unroll
            for (int j = 0; j < 2; j++) {
#pragma unroll
                for (int e = 0; e < acc[i][j].num_elements; e++)
                    acc[i][j].x[e] = fmaxf(acc[i][j].x[e], 0.0f);
                wmma::store_matrix_sync(&out[(size_t)gr * FDIM + n0 + j * 16],
                                        acc[i][j], FDIM, wmma::mem_row_major);
            }
        }
    }
}

// ---------------------------------------------------------------------------
extern "C" void kernel_launch(void* const* d_in, const int* in_sizes, int n_in,
                              void* d_out, int out_size)
{
    const int*   nodes      = (const int*)d_in[0];
    const int*   neigh_idx  = (const int*)d_in[1];
    const float* self_table = (const float*)d_in[2];
    const float* neigh_tab  = (const float*)d_in[3];
    const float* center     = (const float*)d_in[4];
    const float* cmask      = (const float*)d_in[5];
    const float* weight     = (const float*)d_in[6];
    const float* alpha      = (const float*)d_in[7];
    float*       out        = (float*)d_out;

    int B = in_sizes[0];
    int N = in_sizes[3] / FDIM;
    int totalNeigh = in_sizes[1];

    float *pd, *c2;
    __half *prod, *ch, *cl, *wh;
    unsigned char* flag;
    int *list, *count;
    cudaGetSymbolAddress((void**)&prod,  g_prod);
    cudaGetSymbolAddress((void**)&pd,    g_pdot);
    cudaGetSymbolAddress((void**)&c2,    g_c2);
    cudaGetSymbolAddress((void**)&ch,    g_comb_h);
    cudaGetSymbolAddress((void**)&cl,    g_comb_l);
    cudaGetSymbolAddress((void**)&wh,    g_w_h);
    cudaGetSymbolAddress((void**)&flag,  g_flag);
    cudaGetSymbolAddress((void**)&list,  g_list);
    cudaGetSymbolAddress((void**)&count, g_count);

    cudaFuncSetAttribute(gemm_wmma_kernel,
                         cudaFuncAttributeMaxDynamicSharedMemorySize,
                         GSMH * (int)sizeof(__half));

    // 65 W/c2 blocks + 25 flag-zero blocks
    prep_kernel<<<90, 512>>>(weight, wh, center, c2, flag, count);
    flag_kernel<<<(totalNeigh + 255) / 256, 256>>>(neigh_idx, flag, totalNeigh);
    compact_kernel<<<(N + 255) / 256, 256>>>(flag, list, count, N);
    precompute_kernel<<<(N + 31) / 32, 128>>>(neigh_tab, center, alpha, cmask,
                                              c2, list, count, prod, pd);
    row_kernel<<<(B + 7) / 8, 256>>>(nodes, neigh_idx, self_table, alpha,
                                     pd, prod, ch, cl, B);
    gemm_wmma_kernel<<<(B + GBM - 1) / GBM, 256,
                      GSMH * (int)sizeof(__half)>>>(ch, cl, wh, out, B);
}